// round 1
// baseline (speedup 1.0000x reference)
#include <cuda_runtime.h>
#include <math.h>

#define B 192
#define D 2048
#define H 128
#define LOG2PI 1.8378770664093453f

// Scratch (device globals — no allocation allowed)
__device__ __align__(16) float g_h1[B * 2 * H];
__device__ __align__(16) float g_h2[B * 2 * H];
__device__ __align__(16) float g_mu[B * D];
__device__ __align__(16) float g_scale[B * D];
__device__ float g_lvpart[B * 8];
__device__ float g_t[B];

// ---------------------------------------------------------------------------
// Kernel 1: h1 = relu(q @ w1^T + b1) for both heads (cols 0..127 mu, 128..255 lv)
// warp-per-output, K=2048 via float4 + shfl reduce. 49152 outputs -> 6144 blocks.
// ---------------------------------------------------------------------------
__global__ void __launch_bounds__(256) gemm1_kernel(
    const float* __restrict__ q,
    const float* __restrict__ mw, const float* __restrict__ mb,
    const float* __restrict__ lw, const float* __restrict__ lb)
{
    int warp = blockIdx.x * 8 + (threadIdx.x >> 5);
    int lane = threadIdx.x & 31;
    int row = warp >> 8;     // / 256
    int col = warp & 255;

    const float4* q4 = (const float4*)(q + (size_t)row * D);
    const float4* w4;
    float bias;
    if (col < H) { w4 = (const float4*)(mw + (size_t)col * D);       bias = mb[col];     }
    else         { w4 = (const float4*)(lw + (size_t)(col - H) * D); bias = lb[col - H]; }

    float acc = 0.f;
    #pragma unroll
    for (int it = 0; it < (D / 4) / 32; ++it) {
        float4 a = q4[lane + it * 32];
        float4 b = w4[lane + it * 32];
        acc += a.x * b.x + a.y * b.y + a.z * b.z + a.w * b.w;
    }
    #pragma unroll
    for (int o = 16; o; o >>= 1) acc += __shfl_xor_sync(0xffffffffu, acc, o);
    if (lane == 0) g_h1[row * 256 + col] = fmaxf(acc + bias, 0.f);
}

// ---------------------------------------------------------------------------
// Kernel 2: h2 = relu(h1 @ w2^T + b2), block per row (192 blocks x 256 threads)
// ---------------------------------------------------------------------------
__global__ void __launch_bounds__(256) gemm2_kernel(
    const float* __restrict__ mw, const float* __restrict__ mb,
    const float* __restrict__ lw, const float* __restrict__ lb)
{
    __shared__ float s[256];
    int row = blockIdx.x;
    int tid = threadIdx.x;
    s[tid] = g_h1[row * 256 + tid];
    __syncthreads();

    float acc;
    const float* w;
    const float* h;
    if (tid < H) { acc = mb[tid];     w = mw + (size_t)tid * H;       h = s;     }
    else         { acc = lb[tid - H]; w = lw + (size_t)(tid - H) * H; h = s + H; }
    #pragma unroll 16
    for (int k = 0; k < H; ++k) acc += h[k] * w[k];
    g_h2[row * 256 + tid] = fmaxf(acc, 0.f);
}

// ---------------------------------------------------------------------------
// Kernel 3: mu = relu(h2_mu @ w3^T + b3), lv = relu(h2_lv @ w3'^T + b3')
// Writes g_mu, g_scale = exp(0.25*lv), and per-block partial sum of lv
// (deterministic: fixed block -> fixed slot, no atomics).
// grid = (8 d-tiles, 192 rows) x 256 threads.
// ---------------------------------------------------------------------------
__global__ void __launch_bounds__(256) gemm3_kernel(
    const float* __restrict__ mw, const float* __restrict__ mb,
    const float* __restrict__ lw, const float* __restrict__ lb)
{
    __shared__ float s[256];
    __shared__ float red[8];
    int row = blockIdx.y;
    int tid = threadIdx.x;
    s[tid] = g_h2[row * 256 + tid];
    __syncthreads();

    int d = blockIdx.x * 256 + tid;
    float am = mb[d];
    float al = lb[d];
    const float* wm = mw + (size_t)d * H;
    const float* wl = lw + (size_t)d * H;
    #pragma unroll 16
    for (int k = 0; k < H; ++k) {
        am += s[k]       * wm[k];
        al += s[128 + k] * wl[k];
    }
    am = fmaxf(am, 0.f);
    al = fmaxf(al, 0.f);
    g_mu[row * D + d]    = am;
    g_scale[row * D + d] = expf(0.25f * al);

    // block-reduce lv for logdet
    float v = al;
    #pragma unroll
    for (int o = 16; o; o >>= 1) v += __shfl_xor_sync(0xffffffffu, v, o);
    if ((tid & 31) == 0) red[tid >> 5] = v;
    __syncthreads();
    if (tid == 0) {
        float r = 0.f;
        #pragma unroll
        for (int k = 0; k < 8; ++k) r += red[k];
        g_lvpart[row * 8 + blockIdx.x] = r;
    }
}

// ---------------------------------------------------------------------------
// Kernel 4: t[j] = -0.25 * sum(lv[j,:]) - 0.5 * D * log(2pi)
// ---------------------------------------------------------------------------
__global__ void finalize_kernel()
{
    int j = threadIdx.x;
    if (j < B) {
        float sum = 0.f;
        #pragma unroll
        for (int k = 0; k < 8; ++k) sum += g_lvpart[j * 8 + k];
        g_t[j] = -0.25f * sum - 0.5f * (float)D * LOG2PI;
    }
}

// ---------------------------------------------------------------------------
// Kernel 5 (HBM-bound mainloop): one block per (i,j) row of eps.
//   p[i,j,:] = mu[j,:] + eps[i,j,:] * scale[j,:]
//   log_prob[i,j] = -0.5 * sum(eps^2) + t[j]     (maha simplifies to sum eps^2)
// 36864 blocks x 256 threads, float4, 2 iters/thread.
// ---------------------------------------------------------------------------
__global__ void __launch_bounds__(256) main_kernel(
    const float* __restrict__ eps,
    float* __restrict__ p,
    float* __restrict__ lp)
{
    int row = blockIdx.x;        // = i*B + j
    int j = row % B;
    int tid = threadIdx.x;

    const float4* e4 = (const float4*)eps + (size_t)row * (D / 4);
    float4*       p4 = (float4*)p        + (size_t)row * (D / 4);
    const float4* m4 = (const float4*)g_mu    + (size_t)j * (D / 4);
    const float4* s4 = (const float4*)g_scale + (size_t)j * (D / 4);

    float acc = 0.f;
    #pragma unroll
    for (int it = 0; it < 2; ++it) {
        int idx = tid + it * 256;
        float4 e = e4[idx];
        float4 m = m4[idx];
        float4 s = s4[idx];
        float4 o;
        o.x = fmaf(e.x, s.x, m.x);
        o.y = fmaf(e.y, s.y, m.y);
        o.z = fmaf(e.z, s.z, m.z);
        o.w = fmaf(e.w, s.w, m.w);
        p4[idx] = o;
        acc += e.x * e.x + e.y * e.y + e.z * e.z + e.w * e.w;
    }

    __shared__ float red[8];
    #pragma unroll
    for (int o = 16; o; o >>= 1) acc += __shfl_xor_sync(0xffffffffu, acc, o);
    if ((tid & 31) == 0) red[tid >> 5] = acc;
    __syncthreads();
    if (tid == 0) {
        float r = 0.f;
        #pragma unroll
        for (int k = 0; k < 8; ++k) r += red[k];
        lp[row] = -0.5f * r + g_t[j];
    }
}

// ---------------------------------------------------------------------------
extern "C" void kernel_launch(void* const* d_in, const int* in_sizes, int n_in,
                              void* d_out, int out_size)
{
    const float* q     = (const float*)d_in[0];
    const float* eps   = (const float*)d_in[1];
    const float* mu_w1 = (const float*)d_in[2];
    const float* mu_b1 = (const float*)d_in[3];
    const float* mu_w2 = (const float*)d_in[4];
    const float* mu_b2 = (const float*)d_in[5];
    const float* mu_w3 = (const float*)d_in[6];
    const float* mu_b3 = (const float*)d_in[7];
    const float* lv_w1 = (const float*)d_in[8];
    const float* lv_b1 = (const float*)d_in[9];
    const float* lv_w2 = (const float*)d_in[10];
    const float* lv_b2 = (const float*)d_in[11];
    const float* lv_w3 = (const float*)d_in[12];
    const float* lv_b3 = (const float*)d_in[13];

    float* p  = (float*)d_out;                       // [B, B, D]
    float* lp = (float*)d_out + (size_t)B * B * D;   // [B, B]

    gemm1_kernel<<<(B * 256) / 8, 256>>>(q, mu_w1, mu_b1, lv_w1, lv_b1);
    gemm2_kernel<<<B, 256>>>(mu_w2, mu_b2, lv_w2, lv_b2);
    gemm3_kernel<<<dim3(D / 256, B), 256>>>(mu_w3, mu_b3, lv_w3, lv_b3);
    finalize_kernel<<<1, 256>>>();
    main_kernel<<<B * B, 256>>>(eps, p, lp);
}

// round 2
// speedup vs baseline: 2.8731x; 2.8731x over previous
#include <cuda_runtime.h>
#include <math.h>

#define B 192
#define D 2048
#define H 128
#define LOG2PI 1.8378770664093453f

// Scratch (device globals — no allocation allowed)
__device__ __align__(16) float g_h1[B * 2 * H];
__device__ __align__(16) float g_h2[B * 2 * H];
__device__ __align__(16) float g_mu[B * D];
__device__ __align__(16) float g_scale[B * D];
__device__ float g_lvpart[B * 8];
__device__ float g_t[B];

// ---------------------------------------------------------------------------
// Kernel 1: h1 = relu(q @ w1^T + b1), both heads (cols 0..127 mu, 128..255 lv).
// 4x4 register-tiled warps: warp computes 4 rows x 4 cols, lanes split K=2048.
// Reuse factor 4 on both q and w -> ~200 MB L2 traffic instead of 805 MB.
// grid = (8 colgroups-of-8warps, 48 rowgroups) x 256 threads = 384 blocks.
// ---------------------------------------------------------------------------
__global__ void __launch_bounds__(256) gemm1_kernel(
    const float* __restrict__ q,
    const float* __restrict__ mw, const float* __restrict__ mb,
    const float* __restrict__ lw, const float* __restrict__ lb)
{
    int warp = threadIdx.x >> 5;
    int lane = threadIdx.x & 31;
    int cg   = blockIdx.x * 8 + warp;   // colgroup 0..63
    int row0 = blockIdx.y * 4;
    int col0 = cg * 4;

    const float* wbase;
    const float* bbase;
    int clocal;
    if (col0 < H) { wbase = mw; bbase = mb; clocal = col0;     }
    else          { wbase = lw; bbase = lb; clocal = col0 - H; }

    const float4* q4 = (const float4*)q;
    const float4* w4 = (const float4*)wbase;

    float acc[4][4];
    #pragma unroll
    for (int r = 0; r < 4; ++r)
        #pragma unroll
        for (int c = 0; c < 4; ++c) acc[r][c] = 0.f;

    #pragma unroll
    for (int it = 0; it < (D / 4) / 32; ++it) {   // 16 iters
        int k4 = lane + it * 32;
        float4 a[4], b[4];
        #pragma unroll
        for (int r = 0; r < 4; ++r) a[r] = q4[(size_t)(row0 + r) * (D / 4) + k4];
        #pragma unroll
        for (int c = 0; c < 4; ++c) b[c] = w4[(size_t)(clocal + c) * (D / 4) + k4];
        #pragma unroll
        for (int r = 0; r < 4; ++r)
            #pragma unroll
            for (int c = 0; c < 4; ++c)
                acc[r][c] += a[r].x * b[c].x + a[r].y * b[c].y
                           + a[r].z * b[c].z + a[r].w * b[c].w;
    }

    float bv[4];
    #pragma unroll
    for (int c = 0; c < 4; ++c) bv[c] = bbase[clocal + c];

    #pragma unroll
    for (int r = 0; r < 4; ++r)
        #pragma unroll
        for (int c = 0; c < 4; ++c) {
            float v = acc[r][c];
            #pragma unroll
            for (int o = 16; o; o >>= 1) v += __shfl_xor_sync(0xffffffffu, v, o);
            if (lane == 0)
                g_h1[(row0 + r) * 256 + col0 + c] = fmaxf(v + bv[c], 0.f);
        }
}

// ---------------------------------------------------------------------------
// Kernel 2: h2 = relu(h1 @ w2^T + b2), block per row (tiny: 25 MB L2 total)
// ---------------------------------------------------------------------------
__global__ void __launch_bounds__(256) gemm2_kernel(
    const float* __restrict__ mw, const float* __restrict__ mb,
    const float* __restrict__ lw, const float* __restrict__ lb)
{
    __shared__ float s[256];
    int row = blockIdx.x;
    int tid = threadIdx.x;
    s[tid] = g_h1[row * 256 + tid];
    __syncthreads();

    float acc;
    const float* w;
    const float* h;
    if (tid < H) { acc = mb[tid];     w = mw + (size_t)tid * H;       h = s;     }
    else         { acc = lb[tid - H]; w = lw + (size_t)(tid - H) * H; h = s + H; }
    #pragma unroll 16
    for (int k = 0; k < H; ++k) acc += h[k] * w[k];
    g_h2[row * 256 + tid] = fmaxf(acc, 0.f);
}

// ---------------------------------------------------------------------------
// Kernel 3: layer-3 for both heads, 4 rows per block, h2 half-row in smem.
//   mu head  (bx 0..7):  g_mu = relu(...)
//   lv head  (bx 8..15): g_scale = exp(0.25*lv), deterministic partial sum(lv)
// grid = (16 coltiles-of-256, 48 rowgroups) x 256 threads. Weight reuse x4.
// ---------------------------------------------------------------------------
__global__ void __launch_bounds__(256) gemm3_kernel(
    const float* __restrict__ mw, const float* __restrict__ mb,
    const float* __restrict__ lw, const float* __restrict__ lb)
{
    __shared__ float4 s4[4][32];       // 4 rows x 128 floats (one head half)
    __shared__ float red[8][4];

    int tid  = threadIdx.x;
    int row0 = blockIdx.y * 4;
    int head = blockIdx.x >> 3;        // 0 = mu, 1 = lv

    if (tid < 128) {
        int r  = tid >> 5;
        int kk = tid & 31;
        s4[r][kk] = ((const float4*)(g_h2 + (row0 + r) * 256 + head * H))[kk];
    }
    __syncthreads();

    int d = (blockIdx.x & 7) * 256 + tid;         // 0..2047 within head
    const float* wrow = (head ? lw : mw) + (size_t)d * H;
    const float* bptr = head ? lb : mb;

    float acc0 = 0.f, acc1 = 0.f, acc2 = 0.f, acc3 = 0.f;
    #pragma unroll
    for (int kk = 0; kk < 32; ++kk) {
        float4 w = ((const float4*)wrow)[kk];
        float4 h0 = s4[0][kk], h1 = s4[1][kk], h2v = s4[2][kk], h3 = s4[3][kk];
        acc0 += w.x * h0.x + w.y * h0.y + w.z * h0.z + w.w * h0.w;
        acc1 += w.x * h1.x + w.y * h1.y + w.z * h1.z + w.w * h1.w;
        acc2 += w.x * h2v.x + w.y * h2v.y + w.z * h2v.z + w.w * h2v.w;
        acc3 += w.x * h3.x + w.y * h3.y + w.z * h3.z + w.w * h3.w;
    }
    float bias = bptr[d];
    float v[4] = { fmaxf(acc0 + bias, 0.f), fmaxf(acc1 + bias, 0.f),
                   fmaxf(acc2 + bias, 0.f), fmaxf(acc3 + bias, 0.f) };

    if (!head) {
        #pragma unroll
        for (int r = 0; r < 4; ++r)
            g_mu[(size_t)(row0 + r) * D + d] = v[r];
    } else {
        #pragma unroll
        for (int r = 0; r < 4; ++r)
            g_scale[(size_t)(row0 + r) * D + d] = expf(0.25f * v[r]);

        // deterministic block-reduce of lv over this block's 256 cols, per row
        int lane = tid & 31, wid = tid >> 5;
        #pragma unroll
        for (int r = 0; r < 4; ++r) {
            float s = v[r];
            #pragma unroll
            for (int o = 16; o; o >>= 1) s += __shfl_xor_sync(0xffffffffu, s, o);
            if (lane == 0) red[wid][r] = s;
        }
        __syncthreads();
        if (tid == 0) {
            #pragma unroll
            for (int r = 0; r < 4; ++r) {
                float s = 0.f;
                #pragma unroll
                for (int k = 0; k < 8; ++k) s += red[k][r];
                g_lvpart[(row0 + r) * 8 + (blockIdx.x & 7)] = s;
            }
        }
    }
}

// ---------------------------------------------------------------------------
// Kernel 4: t[j] = -0.25 * sum(lv[j,:]) - 0.5 * D * log(2pi)
// ---------------------------------------------------------------------------
__global__ void finalize_kernel()
{
    int j = threadIdx.x;
    if (j < B) {
        float sum = 0.f;
        #pragma unroll
        for (int k = 0; k < 8; ++k) sum += g_lvpart[j * 8 + k];
        g_t[j] = -0.25f * sum - 0.5f * (float)D * LOG2PI;
    }
}

// ---------------------------------------------------------------------------
// Kernel 5 (HBM-bound mainloop): one block per (i,j) row of eps.
//   p[i,j,:] = mu[j,:] + eps[i,j,:] * scale[j,:]
//   log_prob[i,j] = -0.5 * sum(eps^2) + t[j]
// __ldcs / __stcs keep the 604 MB one-touch stream from evicting mu/scale
// (3 MB, reused 192x) out of L2.
// ---------------------------------------------------------------------------
__global__ void __launch_bounds__(256) main_kernel(
    const float* __restrict__ eps,
    float* __restrict__ p,
    float* __restrict__ lp)
{
    int row = blockIdx.x;        // = i*B + j
    int j = row % B;
    int tid = threadIdx.x;

    const float4* e4 = (const float4*)eps + (size_t)row * (D / 4);
    float4*       p4 = (float4*)p        + (size_t)row * (D / 4);
    const float4* m4 = (const float4*)g_mu    + (size_t)j * (D / 4);
    const float4* s4 = (const float4*)g_scale + (size_t)j * (D / 4);

    float acc = 0.f;
    #pragma unroll
    for (int it = 0; it < 2; ++it) {
        int idx = tid + it * 256;
        float4 e = __ldcs(&e4[idx]);
        float4 m = m4[idx];
        float4 s = s4[idx];
        float4 o;
        o.x = fmaf(e.x, s.x, m.x);
        o.y = fmaf(e.y, s.y, m.y);
        o.z = fmaf(e.z, s.z, m.z);
        o.w = fmaf(e.w, s.w, m.w);
        __stcs(&p4[idx], o);
        acc += e.x * e.x + e.y * e.y + e.z * e.z + e.w * e.w;
    }

    __shared__ float red[8];
    #pragma unroll
    for (int o = 16; o; o >>= 1) acc += __shfl_xor_sync(0xffffffffu, acc, o);
    if ((tid & 31) == 0) red[tid >> 5] = acc;
    __syncthreads();
    if (tid == 0) {
        float r = 0.f;
        #pragma unroll
        for (int k = 0; k < 8; ++k) r += red[k];
        lp[row] = -0.5f * r + g_t[j];
    }
}

// ---------------------------------------------------------------------------
extern "C" void kernel_launch(void* const* d_in, const int* in_sizes, int n_in,
                              void* d_out, int out_size)
{
    const float* q     = (const float*)d_in[0];
    const float* eps   = (const float*)d_in[1];
    const float* mu_w1 = (const float*)d_in[2];
    const float* mu_b1 = (const float*)d_in[3];
    const float* mu_w2 = (const float*)d_in[4];
    const float* mu_b2 = (const float*)d_in[5];
    const float* mu_w3 = (const float*)d_in[6];
    const float* mu_b3 = (const float*)d_in[7];
    const float* lv_w1 = (const float*)d_in[8];
    const float* lv_b1 = (const float*)d_in[9];
    const float* lv_w2 = (const float*)d_in[10];
    const float* lv_b2 = (const float*)d_in[11];
    const float* lv_w3 = (const float*)d_in[12];
    const float* lv_b3 = (const float*)d_in[13];

    float* p  = (float*)d_out;                       // [B, B, D]
    float* lp = (float*)d_out + (size_t)B * B * D;   // [B, B]

    gemm1_kernel<<<dim3(8, 48), 256>>>(q, mu_w1, mu_b1, lv_w1, lv_b1);
    gemm2_kernel<<<B, 256>>>(mu_w2, mu_b2, lv_w2, lv_b2);
    gemm3_kernel<<<dim3(16, 48), 256>>>(mu_w3, mu_b3, lv_w3, lv_b3);
    finalize_kernel<<<1, 256>>>();
    main_kernel<<<B * B, 256>>>(eps, p, lp);
}